// round 10
// baseline (speedup 1.0000x reference)
#include <cuda_runtime.h>

#define G     8
#define CIN   64
#define COUT  64
#define KS    7
#define PAD   3
#define H     56
#define W     56
#define B     4

#define TH    8
#define TRW   (TH + KS - 1)   // 14
#define SP    68              // smem row stride (floats); 68*4 bytes, 16B-multiple

#define PH    62              // padded rows
#define PWS   64              // padded row stride (floats) in gmem

// scratch (allocation-free rule)
__device__ float g_q[B*COUT*H*W];          // interior 56x56, float4-aligned rows
__device__ float g_kp[B*COUT*PH*PWS];      // padded k, halo = bk
__device__ float g_vp[B*COUT*PH*PWS];      // padded v, halo = bv

#define EX2F(dst, src) asm("ex2.approx.ftz.f32 %0, %1;" : "=f"(dst) : "f"(src))

// ---------------------------------------------------------------------------
// Kernel 0: fill halo cells of g_kp/g_vp with biases.
// 832 cells per (b,c): 6 full halo rows (64 cols) + 56 interior rows x 8 edge
// cols {0,1,2, 59..63}. Total threads = 4*64*832 = 212,992 = 832 x 256 exact.
// ---------------------------------------------------------------------------
__global__ __launch_bounds__(256)
void halo_kernel(const float* __restrict__ bk, const float* __restrict__ bv) {
    int idx = blockIdx.x * 256 + threadIdx.x;
    int local = idx % 832;
    int cc = idx / 832;
    int c = cc & 63;
    int b = cc >> 6;
    int pr, pc;
    if (local < 384) {                 // full halo rows
        int rr = local >> 6;           // 0..5
        pc = local & 63;
        pr = (rr < 3) ? rr : rr + 56;  // {0,1,2} or {59,60,61}
    } else {
        int l2 = local - 384;          // 0..447
        pr = (l2 >> 3) + 3;            // 3..58
        int ci = l2 & 7;
        pc = (ci < 3) ? ci : ci + 56;  // {0,1,2} or {59..63}
    }
    int gi = ((b*COUT + c)*PH + pr)*PWS + pc;
    g_kp[gi] = bk[c];
    g_vp[gi] = bv[c];
}

// ---------------------------------------------------------------------------
// Kernel 1: fused grouped 1x1 conv, 2 channels x 4 cols per thread.
// q -> interior float4 layout; k/v -> padded layout (scalar stores, misaligned
// by the +3 pad). log2(e) folded into wq.
// ---------------------------------------------------------------------------
__global__ __launch_bounds__(256)
void qkv_kernel(const float* __restrict__ x,
                const float* __restrict__ wq,
                const float* __restrict__ wk,
                const float* __restrict__ bk,
                const float* __restrict__ wv,
                const float* __restrict__ bv) {
    const float LOG2E = 1.4426950408889634f;
    int idx = blockIdx.x * 256 + threadIdx.x;          // 100,352 threads
    int t = idx / 14;
    int j = idx - t*14;
    int h = t % 56;  t /= 56;
    int dp = t % 4;  t /= 4;
    int g = t % 8;
    int b = t / 8;
    int c0 = g*8 + dp;
    int c1 = c0 + 4;

    const float4* xp = (const float4*)x + ((b*CIN + g*8)*H + h)*14 + j;

    float kb0 = __ldg(&bk[c0]), kb1 = __ldg(&bk[c1]);
    float vb0 = __ldg(&bv[c0]), vb1 = __ldg(&bv[c1]);
    float4 aq0 = make_float4(0.f,0.f,0.f,0.f), aq1 = aq0;
    float4 ak0 = make_float4(kb0,kb0,kb0,kb0), ak1 = make_float4(kb1,kb1,kb1,kb1);
    float4 av0 = make_float4(vb0,vb0,vb0,vb0), av1 = make_float4(vb1,vb1,vb1,vb1);

    #pragma unroll
    for (int i = 0; i < 8; i++) {
        float4 xv = __ldg(xp + i*784);
        float w_q0 = __ldg(&wq[c0*8 + i]) * LOG2E;
        float w_k0 = __ldg(&wk[c0*8 + i]);
        float w_v0 = __ldg(&wv[c0*8 + i]);
        float w_q1 = __ldg(&wq[c1*8 + i]) * LOG2E;
        float w_k1 = __ldg(&wk[c1*8 + i]);
        float w_v1 = __ldg(&wv[c1*8 + i]);
        aq0.x = fmaf(w_q0, xv.x, aq0.x); aq0.y = fmaf(w_q0, xv.y, aq0.y);
        aq0.z = fmaf(w_q0, xv.z, aq0.z); aq0.w = fmaf(w_q0, xv.w, aq0.w);
        ak0.x = fmaf(w_k0, xv.x, ak0.x); ak0.y = fmaf(w_k0, xv.y, ak0.y);
        ak0.z = fmaf(w_k0, xv.z, ak0.z); ak0.w = fmaf(w_k0, xv.w, ak0.w);
        av0.x = fmaf(w_v0, xv.x, av0.x); av0.y = fmaf(w_v0, xv.y, av0.y);
        av0.z = fmaf(w_v0, xv.z, av0.z); av0.w = fmaf(w_v0, xv.w, av0.w);
        aq1.x = fmaf(w_q1, xv.x, aq1.x); aq1.y = fmaf(w_q1, xv.y, aq1.y);
        aq1.z = fmaf(w_q1, xv.z, aq1.z); aq1.w = fmaf(w_q1, xv.w, aq1.w);
        ak1.x = fmaf(w_k1, xv.x, ak1.x); ak1.y = fmaf(w_k1, xv.y, ak1.y);
        ak1.z = fmaf(w_k1, xv.z, ak1.z); ak1.w = fmaf(w_k1, xv.w, ak1.w);
        av1.x = fmaf(w_v1, xv.x, av1.x); av1.y = fmaf(w_v1, xv.y, av1.y);
        av1.z = fmaf(w_v1, xv.z, av1.z); av1.w = fmaf(w_v1, xv.w, av1.w);
    }
    int oq0 = ((b*COUT + c0)*H + h)*14 + j;
    int oq1 = ((b*COUT + c1)*H + h)*14 + j;
    ((float4*)g_q)[oq0] = aq0; ((float4*)g_q)[oq1] = aq1;

    // padded k/v stores (row h+3, cols 4j+3 .. 4j+6)
    int pk0 = ((b*COUT + c0)*PH + (h + PAD))*PWS + 4*j + PAD;
    int pk1 = ((b*COUT + c1)*PH + (h + PAD))*PWS + 4*j + PAD;
    g_kp[pk0+0] = ak0.x; g_kp[pk0+1] = ak0.y; g_kp[pk0+2] = ak0.z; g_kp[pk0+3] = ak0.w;
    g_vp[pk0+0] = av0.x; g_vp[pk0+1] = av0.y; g_vp[pk0+2] = av0.z; g_vp[pk0+3] = av0.w;
    g_kp[pk1+0] = ak1.x; g_kp[pk1+1] = ak1.y; g_kp[pk1+2] = ak1.z; g_kp[pk1+3] = ak1.w;
    g_vp[pk1+0] = av1.x; g_vp[pk1+1] = av1.y; g_vp[pk1+2] = av1.z; g_vp[pk1+3] = av1.w;
}

// ---------------------------------------------------------------------------
// Kernel 2: windowed softmax attention, 2 adjacent outputs/thread (R7 body).
// Staging from padded gmem: exactly one float4 per thread per array,
// branch-free (14 rows x 16 float4 = 224 threads).
// ---------------------------------------------------------------------------
__global__ __launch_bounds__(224, 6)
void attn_kernel(const float* __restrict__ rel_x,
                 const float* __restrict__ rel_y,
                 float* __restrict__ out) {
    __shared__ __align__(16) float ks_[TRW*SP];
    __shared__ __align__(16) float vs_[TRW*SP];

    int ht = blockIdx.x;
    int c  = blockIdx.y;
    int b  = blockIdx.z;
    int h0 = ht * TH;
    int tid = threadIdx.x;
    int d = c & 7;

    int r  = tid / 28;
    int wp = tid - r*28;
    int h  = h0 + r;
    int w0 = wp * 2;
    int cbase = (b*COUT + c)*H;

    // prefetch per-thread state (overlaps staging latency)
    float2 qv = ((const float2*)g_q)[(cbase + h)*28 + wp];  // pre-scaled by log2e
    float relv[7];
    #pragma unroll
    for (int jj = 0; jj < 7; jj++)
        relv[jj] = (d < 4) ? __ldg(&rel_x[d*KS + jj]) : __ldg(&rel_y[(d-4)*KS + jj]);

    // branch-free vector staging: thread -> (row pr, float4 col c4)
    {
        int pr = tid >> 4;          // 0..13
        int c4 = tid & 15;          // 0..15
        int gbase = ((b*COUT + c)*PH + (h0 + pr))*PWS + 4*c4;
        float4 kk4 = *(const float4*)(g_kp + gbase);
        float4 vv4 = *(const float4*)(g_vp + gbase);
        *(float4*)(ks_ + pr*SP + 4*c4) = kk4;
        *(float4*)(vs_ + pr*SP + 4*c4) = vv4;
    }
    __syncthreads();

    float q0 = qv.x, q1 = qv.y;

    float s0a = 0.f, s0b = 0.f, s1a = 0.f, s1b = 0.f;
    float o0a = 0.f, o0b = 0.f, o1a = 0.f, o1b = 0.f;

    if (d < 4) {
        #pragma unroll
        for (int jy = 0; jy < KS; jy++) {
            const float2* kp = (const float2*)(ks_ + (r + jy)*SP + w0);
            const float2* vp = (const float2*)(vs_ + (r + jy)*SP + w0);
            float2 ka = kp[0], kc = kp[1], ke = kp[2], kg = kp[3];
            float2 va = vp[0], vc = vp[1], ve = vp[2], vg = vp[3];
            float a0 = q0 * relv[jy];
            float a1 = q1 * relv[jy];
            float e;
            EX2F(e, fmaf(q0, ka.x, a0)); s0a += e; o0a = fmaf(e, va.x, o0a);
            EX2F(e, fmaf(q0, ka.y, a0)); s0b += e; o0b = fmaf(e, va.y, o0b);
            EX2F(e, fmaf(q0, kc.x, a0)); s0a += e; o0a = fmaf(e, vc.x, o0a);
            EX2F(e, fmaf(q0, kc.y, a0)); s0b += e; o0b = fmaf(e, vc.y, o0b);
            EX2F(e, fmaf(q0, ke.x, a0)); s0a += e; o0a = fmaf(e, ve.x, o0a);
            EX2F(e, fmaf(q0, ke.y, a0)); s0b += e; o0b = fmaf(e, ve.y, o0b);
            EX2F(e, fmaf(q0, kg.x, a0)); s0a += e; o0a = fmaf(e, vg.x, o0a);
            EX2F(e, fmaf(q1, ka.y, a1)); s1a += e; o1a = fmaf(e, va.y, o1a);
            EX2F(e, fmaf(q1, kc.x, a1)); s1b += e; o1b = fmaf(e, vc.x, o1b);
            EX2F(e, fmaf(q1, kc.y, a1)); s1a += e; o1a = fmaf(e, vc.y, o1a);
            EX2F(e, fmaf(q1, ke.x, a1)); s1b += e; o1b = fmaf(e, ve.x, o1b);
            EX2F(e, fmaf(q1, ke.y, a1)); s1a += e; o1a = fmaf(e, ve.y, o1a);
            EX2F(e, fmaf(q1, kg.x, a1)); s1b += e; o1b = fmaf(e, vg.x, o1b);
            EX2F(e, fmaf(q1, kg.y, a1)); s1a += e; o1a = fmaf(e, vg.y, o1a);
        }
    } else {
        #pragma unroll
        for (int jy = 0; jy < KS; jy++) {
            const float2* kp = (const float2*)(ks_ + (r + jy)*SP + w0);
            const float2* vp = (const float2*)(vs_ + (r + jy)*SP + w0);
            float2 ka = kp[0], kc = kp[1], ke = kp[2], kg = kp[3];
            float2 va = vp[0], vc = vp[1], ve = vp[2], vg = vp[3];
            float e;
            EX2F(e, fmaf(q0, ka.x, q0*relv[0])); s0a += e; o0a = fmaf(e, va.x, o0a);
            EX2F(e, fmaf(q0, ka.y, q0*relv[1])); s0b += e; o0b = fmaf(e, va.y, o0b);
            EX2F(e, fmaf(q0, kc.x, q0*relv[2])); s0a += e; o0a = fmaf(e, vc.x, o0a);
            EX2F(e, fmaf(q0, kc.y, q0*relv[3])); s0b += e; o0b = fmaf(e, vc.y, o0b);
            EX2F(e, fmaf(q0, ke.x, q0*relv[4])); s0a += e; o0a = fmaf(e, ve.x, o0a);
            EX2F(e, fmaf(q0, ke.y, q0*relv[5])); s0b += e; o0b = fmaf(e, ve.y, o0b);
            EX2F(e, fmaf(q0, kg.x, q0*relv[6])); s0a += e; o0a = fmaf(e, vg.x, o0a);
            EX2F(e, fmaf(q1, ka.y, q1*relv[0])); s1a += e; o1a = fmaf(e, va.y, o1a);
            EX2F(e, fmaf(q1, kc.x, q1*relv[1])); s1b += e; o1b = fmaf(e, vc.x, o1b);
            EX2F(e, fmaf(q1, kc.y, q1*relv[2])); s1a += e; o1a = fmaf(e, vc.y, o1a);
            EX2F(e, fmaf(q1, ke.x, q1*relv[3])); s1b += e; o1b = fmaf(e, ve.x, o1b);
            EX2F(e, fmaf(q1, ke.y, q1*relv[4])); s1a += e; o1a = fmaf(e, ve.y, o1a);
            EX2F(e, fmaf(q1, kg.x, q1*relv[5])); s1b += e; o1b = fmaf(e, vg.x, o1b);
            EX2F(e, fmaf(q1, kg.y, q1*relv[6])); s1a += e; o1a = fmaf(e, vg.y, o1a);
        }
    }

    float2 res;
    res.x = __fdividef(o0a + o0b, s0a + s0b);
    res.y = __fdividef(o1a + o1b, s1a + s1b);
    *(float2*)&out[(cbase + h)*W + w0] = res;
}

// ---------------------------------------------------------------------------
extern "C" void kernel_launch(void* const* d_in, const int* in_sizes, int n_in,
                              void* d_out, int out_size) {
    const float* x     = (const float*)d_in[0];
    const float* wq    = (const float*)d_in[1];
    const float* wk    = (const float*)d_in[2];
    const float* bk    = (const float*)d_in[3];
    const float* wv    = (const float*)d_in[4];
    const float* bv    = (const float*)d_in[5];
    const float* rel_x = (const float*)d_in[6];
    const float* rel_y = (const float*)d_in[7];
    float* out = (float*)d_out;

    halo_kernel<<<832, 256>>>(bk, bv);                 // fills padded halos (disjoint from qkv writes)
    qkv_kernel<<<392, 256>>>(x, wq, wk, bk, wv, bv);

    dim3 grid(H/TH, COUT, B);   // 1792 blocks
    attn_kernel<<<grid, 224>>>(rel_x, rel_y, out);
}

// round 11
// speedup vs baseline: 1.1133x; 1.1133x over previous
#include <cuda_runtime.h>

#define G     8
#define CIN   64
#define COUT  64
#define KS    7
#define PAD   3
#define H     56
#define W     56
#define B     4

#define TH    8
#define TRW   (TH + KS - 1)   // 14
#define SP    68              // smem row stride (floats); 16B multiple

#define PH    62              // padded rows
#define PWS   64              // padded row stride (floats) in gmem

#define NQKV     100352       // qkv threads
#define NHALO    212992       // halo cells per array (4*64*832)

// scratch (allocation-free rule)
__device__ float g_q[B*COUT*H*W];          // interior 56x56, float4 rows
__device__ float g_kp[B*COUT*PH*PWS];      // padded k, halo = bk
__device__ float g_vp[B*COUT*PH*PWS];      // padded v, halo = bv

#define EX2F(dst, src) asm("ex2.approx.ftz.f32 %0, %1;" : "=f"(dst) : "f"(src))

// ---------------------------------------------------------------------------
// Kernel 1: fused grouped 1x1 conv (2 channels x 4 cols / thread) + halo fill.
// q -> interior float4 layout; k/v -> padded layout. log2(e) folded into wq.
// Halo cells (bias-valued) are written by the same threads at the end:
// cell = idx + u*NQKV, u in 0..2  (3*NQKV >= NHALO).
// ---------------------------------------------------------------------------
__global__ __launch_bounds__(256)
void qkv_kernel(const float* __restrict__ x,
                const float* __restrict__ wq,
                const float* __restrict__ wk,
                const float* __restrict__ bk,
                const float* __restrict__ wv,
                const float* __restrict__ bv) {
    const float LOG2E = 1.4426950408889634f;
    int idx = blockIdx.x * 256 + threadIdx.x;          // 100,352 threads exact
    int t = idx / 14;
    int j = idx - t*14;
    int h = t % 56;  t /= 56;
    int dp = t % 4;  t /= 4;
    int g = t % 8;
    int b = t / 8;
    int c0 = g*8 + dp;
    int c1 = c0 + 4;

    const float4* xp = (const float4*)x + ((b*CIN + g*8)*H + h)*14 + j;

    float kb0 = __ldg(&bk[c0]), kb1 = __ldg(&bk[c1]);
    float vb0 = __ldg(&bv[c0]), vb1 = __ldg(&bv[c1]);
    float4 aq0 = make_float4(0.f,0.f,0.f,0.f), aq1 = aq0;
    float4 ak0 = make_float4(kb0,kb0,kb0,kb0), ak1 = make_float4(kb1,kb1,kb1,kb1);
    float4 av0 = make_float4(vb0,vb0,vb0,vb0), av1 = make_float4(vb1,vb1,vb1,vb1);

    #pragma unroll
    for (int i = 0; i < 8; i++) {
        float4 xv = __ldg(xp + i*784);
        float w_q0 = __ldg(&wq[c0*8 + i]) * LOG2E;
        float w_k0 = __ldg(&wk[c0*8 + i]);
        float w_v0 = __ldg(&wv[c0*8 + i]);
        float w_q1 = __ldg(&wq[c1*8 + i]) * LOG2E;
        float w_k1 = __ldg(&wk[c1*8 + i]);
        float w_v1 = __ldg(&wv[c1*8 + i]);
        aq0.x = fmaf(w_q0, xv.x, aq0.x); aq0.y = fmaf(w_q0, xv.y, aq0.y);
        aq0.z = fmaf(w_q0, xv.z, aq0.z); aq0.w = fmaf(w_q0, xv.w, aq0.w);
        ak0.x = fmaf(w_k0, xv.x, ak0.x); ak0.y = fmaf(w_k0, xv.y, ak0.y);
        ak0.z = fmaf(w_k0, xv.z, ak0.z); ak0.w = fmaf(w_k0, xv.w, ak0.w);
        av0.x = fmaf(w_v0, xv.x, av0.x); av0.y = fmaf(w_v0, xv.y, av0.y);
        av0.z = fmaf(w_v0, xv.z, av0.z); av0.w = fmaf(w_v0, xv.w, av0.w);
        aq1.x = fmaf(w_q1, xv.x, aq1.x); aq1.y = fmaf(w_q1, xv.y, aq1.y);
        aq1.z = fmaf(w_q1, xv.z, aq1.z); aq1.w = fmaf(w_q1, xv.w, aq1.w);
        ak1.x = fmaf(w_k1, xv.x, ak1.x); ak1.y = fmaf(w_k1, xv.y, ak1.y);
        ak1.z = fmaf(w_k1, xv.z, ak1.z); ak1.w = fmaf(w_k1, xv.w, ak1.w);
        av1.x = fmaf(w_v1, xv.x, av1.x); av1.y = fmaf(w_v1, xv.y, av1.y);
        av1.z = fmaf(w_v1, xv.z, av1.z); av1.w = fmaf(w_v1, xv.w, av1.w);
    }
    int oq0 = ((b*COUT + c0)*H + h)*14 + j;
    int oq1 = ((b*COUT + c1)*H + h)*14 + j;
    ((float4*)g_q)[oq0] = aq0; ((float4*)g_q)[oq1] = aq1;

    // padded k/v stores (row h+3, cols 4j+3 .. 4j+6)
    int pk0 = ((b*COUT + c0)*PH + (h + PAD))*PWS + 4*j + PAD;
    int pk1 = ((b*COUT + c1)*PH + (h + PAD))*PWS + 4*j + PAD;
    g_kp[pk0+0] = ak0.x; g_kp[pk0+1] = ak0.y; g_kp[pk0+2] = ak0.z; g_kp[pk0+3] = ak0.w;
    g_vp[pk0+0] = av0.x; g_vp[pk0+1] = av0.y; g_vp[pk0+2] = av0.z; g_vp[pk0+3] = av0.w;
    g_kp[pk1+0] = ak1.x; g_kp[pk1+1] = ak1.y; g_kp[pk1+2] = ak1.z; g_kp[pk1+3] = ak1.w;
    g_vp[pk1+0] = av1.x; g_vp[pk1+1] = av1.y; g_vp[pk1+2] = av1.z; g_vp[pk1+3] = av1.w;

    // ---- halo fill (bias values), folded into this kernel ----
    #pragma unroll
    for (int u = 0; u < 3; u++) {
        int cell = idx + u*NQKV;
        if (cell < NHALO) {
            int cc = cell / 832;
            int local = cell - cc*832;
            int hc = cc & 63;
            int hb = cc >> 6;
            int pr, pc;
            if (local < 384) {                 // full halo rows
                int rr = local >> 6;           // 0..5
                pc = local & 63;
                pr = (rr < 3) ? rr : rr + 56;  // rows {0,1,2,59,60,61}
            } else {
                int l2 = local - 384;          // 0..447
                pr = (l2 >> 3) + 3;            // rows 3..58
                int ci = l2 & 7;
                pc = (ci < 3) ? ci : ci + 56;  // cols {0,1,2,59..63}
            }
            int gi = ((hb*COUT + hc)*PH + pr)*PWS + pc;
            g_kp[gi] = __ldg(&bk[hc]);
            g_vp[gi] = __ldg(&bv[hc]);
        }
    }
}

// ---------------------------------------------------------------------------
// Kernel 2: windowed softmax attention, 2 adjacent outputs/thread (R7 body).
// Branch-free vector staging: 14 rows x 16 float4 = 224 threads, exactly one
// LDG.128 + STS.128 per array per thread.
// ---------------------------------------------------------------------------
__global__ __launch_bounds__(224, 6)
void attn_kernel(const float* __restrict__ rel_x,
                 const float* __restrict__ rel_y,
                 float* __restrict__ out) {
    __shared__ __align__(16) float ks_[TRW*SP];
    __shared__ __align__(16) float vs_[TRW*SP];

    int ht = blockIdx.x;
    int c  = blockIdx.y;
    int b  = blockIdx.z;
    int h0 = ht * TH;
    int tid = threadIdx.x;
    int d = c & 7;

    int r  = tid / 28;
    int wp = tid - r*28;
    int h  = h0 + r;
    int w0 = wp * 2;
    int cbase = (b*COUT + c)*H;

    // prefetch per-thread state (overlaps staging latency)
    float2 qv = ((const float2*)g_q)[(cbase + h)*28 + wp];  // pre-scaled by log2e
    float relv[7];
    #pragma unroll
    for (int jj = 0; jj < 7; jj++)
        relv[jj] = (d < 4) ? __ldg(&rel_x[d*KS + jj]) : __ldg(&rel_y[(d-4)*KS + jj]);

    // branch-free vector staging
    {
        int pr = tid >> 4;          // 0..13
        int c4 = tid & 15;          // 0..15
        int gbase = ((b*COUT + c)*PH + (h0 + pr))*PWS + 4*c4;
        float4 kk4 = *(const float4*)(g_kp + gbase);
        float4 vv4 = *(const float4*)(g_vp + gbase);
        *(float4*)(ks_ + pr*SP + 4*c4) = kk4;
        *(float4*)(vs_ + pr*SP + 4*c4) = vv4;
    }
    __syncthreads();

    float q0 = qv.x, q1 = qv.y;

    float s0a = 0.f, s0b = 0.f, s1a = 0.f, s1b = 0.f;
    float o0a = 0.f, o0b = 0.f, o1a = 0.f, o1b = 0.f;

    if (d < 4) {
        #pragma unroll
        for (int jy = 0; jy < KS; jy++) {
            const float2* kp = (const float2*)(ks_ + (r + jy)*SP + w0);
            const float2* vp = (const float2*)(vs_ + (r + jy)*SP + w0);
            float2 ka = kp[0], kc = kp[1], ke = kp[2], kg = kp[3];
            float2 va = vp[0], vc = vp[1], ve = vp[2], vg = vp[3];
            float a0 = q0 * relv[jy];
            float a1 = q1 * relv[jy];
            float e;
            EX2F(e, fmaf(q0, ka.x, a0)); s0a += e; o0a = fmaf(e, va.x, o0a);
            EX2F(e, fmaf(q0, ka.y, a0)); s0b += e; o0b = fmaf(e, va.y, o0b);
            EX2F(e, fmaf(q0, kc.x, a0)); s0a += e; o0a = fmaf(e, vc.x, o0a);
            EX2F(e, fmaf(q0, kc.y, a0)); s0b += e; o0b = fmaf(e, vc.y, o0b);
            EX2F(e, fmaf(q0, ke.x, a0)); s0a += e; o0a = fmaf(e, ve.x, o0a);
            EX2F(e, fmaf(q0, ke.y, a0)); s0b += e; o0b = fmaf(e, ve.y, o0b);
            EX2F(e, fmaf(q0, kg.x, a0)); s0a += e; o0a = fmaf(e, vg.x, o0a);
            EX2F(e, fmaf(q1, ka.y, a1)); s1a += e; o1a = fmaf(e, va.y, o1a);
            EX2F(e, fmaf(q1, kc.x, a1)); s1b += e; o1b = fmaf(e, vc.x, o1b);
            EX2F(e, fmaf(q1, kc.y, a1)); s1a += e; o1a = fmaf(e, vc.y, o1a);
            EX2F(e, fmaf(q1, ke.x, a1)); s1b += e; o1b = fmaf(e, ve.x, o1b);
            EX2F(e, fmaf(q1, ke.y, a1)); s1a += e; o1a = fmaf(e, ve.y, o1a);
            EX2F(e, fmaf(q1, kg.x, a1)); s1b += e; o1b = fmaf(e, vg.x, o1b);
            EX2F(e, fmaf(q1, kg.y, a1)); s1a += e; o1a = fmaf(e, vg.y, o1a);
        }
    } else {
        #pragma unroll
        for (int jy = 0; jy < KS; jy++) {
            const float2* kp = (const float2*)(ks_ + (r + jy)*SP + w0);
            const float2* vp = (const float2*)(vs_ + (r + jy)*SP + w0);
            float2 ka = kp[0], kc = kp[1], ke = kp[2], kg = kp[3];
            float2 va = vp[0], vc = vp[1], ve = vp[2], vg = vp[3];
            float e;
            EX2F(e, fmaf(q0, ka.x, q0*relv[0])); s0a += e; o0a = fmaf(e, va.x, o0a);
            EX2F(e, fmaf(q0, ka.y, q0*relv[1])); s0b += e; o0b = fmaf(e, va.y, o0b);
            EX2F(e, fmaf(q0, kc.x, q0*relv[2])); s0a += e; o0a = fmaf(e, vc.x, o0a);
            EX2F(e, fmaf(q0, kc.y, q0*relv[3])); s0b += e; o0b = fmaf(e, vc.y, o0b);
            EX2F(e, fmaf(q0, ke.x, q0*relv[4])); s0a += e; o0a = fmaf(e, ve.x, o0a);
            EX2F(e, fmaf(q0, ke.y, q0*relv[5])); s0b += e; o0b = fmaf(e, ve.y, o0b);
            EX2F(e, fmaf(q0, kg.x, q0*relv[6])); s0a += e; o0a = fmaf(e, vg.x, o0a);
            EX2F(e, fmaf(q1, ka.y, q1*relv[0])); s1a += e; o1a = fmaf(e, va.y, o1a);
            EX2F(e, fmaf(q1, kc.x, q1*relv[1])); s1b += e; o1b = fmaf(e, vc.x, o1b);
            EX2F(e, fmaf(q1, kc.y, q1*relv[2])); s1a += e; o1a = fmaf(e, vc.y, o1a);
            EX2F(e, fmaf(q1, ke.x, q1*relv[3])); s1b += e; o1b = fmaf(e, ve.x, o1b);
            EX2F(e, fmaf(q1, ke.y, q1*relv[4])); s1a += e; o1a = fmaf(e, ve.y, o1a);
            EX2F(e, fmaf(q1, kg.x, q1*relv[5])); s1b += e; o1b = fmaf(e, vg.x, o1b);
            EX2F(e, fmaf(q1, kg.y, q1*relv[6])); s1a += e; o1a = fmaf(e, vg.y, o1a);
        }
    }

    float2 res;
    res.x = __fdividef(o0a + o0b, s0a + s0b);
    res.y = __fdividef(o1a + o1b, s1a + s1b);
    *(float2*)&out[(cbase + h)*W + w0] = res;
}

// ---------------------------------------------------------------------------
extern "C" void kernel_launch(void* const* d_in, const int* in_sizes, int n_in,
                              void* d_out, int out_size) {
    const float* x     = (const float*)d_in[0];
    const float* wq    = (const float*)d_in[1];
    const float* wk    = (const float*)d_in[2];
    const float* bk    = (const float*)d_in[3];
    const float* wv    = (const float*)d_in[4];
    const float* bv    = (const float*)d_in[5];
    const float* rel_x = (const float*)d_in[6];
    const float* rel_y = (const float*)d_in[7];
    float* out = (float*)d_out;

    qkv_kernel<<<392, 256>>>(x, wq, wk, bk, wv, bv);   // conv + halo fill

    dim3 grid(H/TH, COUT, B);   // 1792 blocks
    attn_kernel<<<grid, 224>>>(rel_x, rel_y, out);
}

// round 12
// speedup vs baseline: 1.2137x; 1.0902x over previous
#include <cuda_runtime.h>

#define G     8
#define CIN   64
#define COUT  64
#define KS    7
#define PAD   3
#define H     56
#define W     56
#define B     4

#define TH    8
#define TRW   (TH + KS - 1)   // 14
#define SP    68              // smem row stride (floats); 16B multiple

#define PH    62              // padded rows (3 top, 3 bottom)
#define PWS   64              // padded row stride; LEFT PAD = 4 (cols 0..3 halo, 4..59 interior, 60..63 halo/junk)

#define NQKV      100352      // qkv threads
#define NEDGE     114688      // edge halo cells: 8 cols x 56 rows x 256 (b,c)
#define NFULL     24576       // full-row halo float4 cells: 96 x 256

// scratch (allocation-free rule)
__device__ float g_q[B*COUT*H*W];          // interior 56x56, float4 rows
__device__ float g_kp[B*COUT*PH*PWS];      // padded k (halo = bk)
__device__ float g_vp[B*COUT*PH*PWS];      // padded v (halo = bv)

#define EX2F(dst, src) asm("ex2.approx.ftz.f32 %0, %1;" : "=f"(dst) : "f"(src))

// ---------------------------------------------------------------------------
// Kernel 1: fused grouped 1x1 conv (2 channels x 4 cols / thread) + halo fill.
// k/v -> padded layout with LEFT PAD 4 so interior stores are STG.128.
// log2(e) folded into wq.
// ---------------------------------------------------------------------------
__global__ __launch_bounds__(256)
void qkv_kernel(const float* __restrict__ x,
                const float* __restrict__ wq,
                const float* __restrict__ wk,
                const float* __restrict__ bk,
                const float* __restrict__ wv,
                const float* __restrict__ bv) {
    const float LOG2E = 1.4426950408889634f;
    int idx = blockIdx.x * 256 + threadIdx.x;          // 100,352 threads exact
    int t = idx / 14;
    int j = idx - t*14;
    int h = t % 56;  t /= 56;
    int dp = t % 4;  t /= 4;
    int g = t % 8;
    int b = t / 8;
    int c0 = g*8 + dp;
    int c1 = c0 + 4;

    const float4* xp = (const float4*)x + ((b*CIN + g*8)*H + h)*14 + j;

    float kb0 = __ldg(&bk[c0]), kb1 = __ldg(&bk[c1]);
    float vb0 = __ldg(&bv[c0]), vb1 = __ldg(&bv[c1]);
    float4 aq0 = make_float4(0.f,0.f,0.f,0.f), aq1 = aq0;
    float4 ak0 = make_float4(kb0,kb0,kb0,kb0), ak1 = make_float4(kb1,kb1,kb1,kb1);
    float4 av0 = make_float4(vb0,vb0,vb0,vb0), av1 = make_float4(vb1,vb1,vb1,vb1);

    #pragma unroll
    for (int i = 0; i < 8; i++) {
        float4 xv = __ldg(xp + i*784);
        float w_q0 = __ldg(&wq[c0*8 + i]) * LOG2E;
        float w_k0 = __ldg(&wk[c0*8 + i]);
        float w_v0 = __ldg(&wv[c0*8 + i]);
        float w_q1 = __ldg(&wq[c1*8 + i]) * LOG2E;
        float w_k1 = __ldg(&wk[c1*8 + i]);
        float w_v1 = __ldg(&wv[c1*8 + i]);
        aq0.x = fmaf(w_q0, xv.x, aq0.x); aq0.y = fmaf(w_q0, xv.y, aq0.y);
        aq0.z = fmaf(w_q0, xv.z, aq0.z); aq0.w = fmaf(w_q0, xv.w, aq0.w);
        ak0.x = fmaf(w_k0, xv.x, ak0.x); ak0.y = fmaf(w_k0, xv.y, ak0.y);
        ak0.z = fmaf(w_k0, xv.z, ak0.z); ak0.w = fmaf(w_k0, xv.w, ak0.w);
        av0.x = fmaf(w_v0, xv.x, av0.x); av0.y = fmaf(w_v0, xv.y, av0.y);
        av0.z = fmaf(w_v0, xv.z, av0.z); av0.w = fmaf(w_v0, xv.w, av0.w);
        aq1.x = fmaf(w_q1, xv.x, aq1.x); aq1.y = fmaf(w_q1, xv.y, aq1.y);
        aq1.z = fmaf(w_q1, xv.z, aq1.z); aq1.w = fmaf(w_q1, xv.w, aq1.w);
        ak1.x = fmaf(w_k1, xv.x, ak1.x); ak1.y = fmaf(w_k1, xv.y, ak1.y);
        ak1.z = fmaf(w_k1, xv.z, ak1.z); ak1.w = fmaf(w_k1, xv.w, ak1.w);
        av1.x = fmaf(w_v1, xv.x, av1.x); av1.y = fmaf(w_v1, xv.y, av1.y);
        av1.z = fmaf(w_v1, xv.z, av1.z); av1.w = fmaf(w_v1, xv.w, av1.w);
    }
    int oq0 = ((b*COUT + c0)*H + h)*14 + j;
    int oq1 = ((b*COUT + c1)*H + h)*14 + j;
    ((float4*)g_q)[oq0] = aq0; ((float4*)g_q)[oq1] = aq1;

    // padded aligned k/v stores (row h+3, cols 4j+4 .. 4j+7)
    int pk0 = ((b*COUT + c0)*PH + (h + PAD))*PWS + 4*j + 4;
    int pk1 = ((b*COUT + c1)*PH + (h + PAD))*PWS + 4*j + 4;
    *(float4*)(g_kp + pk0) = ak0;
    *(float4*)(g_vp + pk0) = av0;
    *(float4*)(g_kp + pk1) = ak1;
    *(float4*)(g_vp + pk1) = av1;

    // ---- halo fill ----
    // full halo rows {0,1,2,59,60,61}, 16 float4 each, per (b,c)
    if (idx < NFULL) {
        int bc = idx / 96;
        int local = idx - bc*96;
        int rr = local >> 4;
        int c4 = local & 15;
        int pr = (rr < 3) ? rr : rr + 56;
        int hc = bc & 63, hb = bc >> 6;
        float kbv = __ldg(&bk[hc]);
        float vbv = __ldg(&bv[hc]);
        int gi = ((hb*COUT + hc)*PH + pr)*PWS + 4*c4;
        *(float4*)(g_kp + gi) = make_float4(kbv,kbv,kbv,kbv);
        *(float4*)(g_vp + gi) = make_float4(vbv,vbv,vbv,vbv);
    }
    // edge cols {0..3, 60..63} on interior rows 3..58
    #pragma unroll
    for (int u = 0; u < 2; u++) {
        int cell = idx + u*NQKV;
        if (cell < NEDGE) {
            int bc = cell / 448;
            int local = cell - bc*448;
            int r3 = local >> 3;
            int ci = local & 7;
            int pr = r3 + 3;
            int pc = (ci < 4) ? ci : ci + 56;
            int hc = bc & 63, hb = bc >> 6;
            int gi = ((hb*COUT + hc)*PH + pr)*PWS + pc;
            g_kp[gi] = __ldg(&bk[hc]);
            g_vp[gi] = __ldg(&bv[hc]);
        }
    }
}

// ---------------------------------------------------------------------------
// Kernel 2: windowed softmax attention, 2 adjacent outputs/thread (R7 body).
// Vector staging with +1-column shuffle shift: smem[s] = gmem[s+1], so the
// compute body keeps the original even-aligned float2 tap mapping.
// ---------------------------------------------------------------------------
__global__ __launch_bounds__(224, 6)
void attn_kernel(const float* __restrict__ rel_x,
                 const float* __restrict__ rel_y,
                 float* __restrict__ out) {
    __shared__ __align__(16) float ks_[TRW*SP];
    __shared__ __align__(16) float vs_[TRW*SP];

    int ht = blockIdx.x;
    int c  = blockIdx.y;
    int b  = blockIdx.z;
    int h0 = ht * TH;
    int tid = threadIdx.x;
    int d = c & 7;

    int r  = tid / 28;
    int wp = tid - r*28;
    int h  = h0 + r;
    int w0 = wp * 2;
    int cbase = (b*COUT + c)*H;

    // prefetch per-thread state (overlaps staging latency)
    float2 qv = ((const float2*)g_q)[(cbase + h)*28 + wp];  // pre-scaled by log2e
    float relv[7];
    #pragma unroll
    for (int jj = 0; jj < 7; jj++)
        relv[jj] = (d < 4) ? __ldg(&rel_x[d*KS + jj]) : __ldg(&rel_y[(d-4)*KS + jj]);

    // staging: load gmem float4 [4c4..4c4+3], store smem [4c4..4c4+3] = gmem[4c4+1..4c4+4]
    // (lane 15/31 wrapped shuffle value lands in smem col 63 — never read)
    {
        int pr = tid >> 4;          // 0..13
        int c4 = tid & 15;          // 0..15
        int gbase = ((b*COUT + c)*PH + (h0 + pr))*PWS + 4*c4;
        float4 k4 = *(const float4*)(g_kp + gbase);
        float4 v4 = *(const float4*)(g_vp + gbase);
        float knx = __shfl_down_sync(0xFFFFFFFFu, k4.x, 1);
        float vnx = __shfl_down_sync(0xFFFFFFFFu, v4.x, 1);
        *(float4*)(ks_ + pr*SP + 4*c4) = make_float4(k4.y, k4.z, k4.w, knx);
        *(float4*)(vs_ + pr*SP + 4*c4) = make_float4(v4.y, v4.z, v4.w, vnx);
    }
    __syncthreads();

    float q0 = qv.x, q1 = qv.y;

    float s0a = 0.f, s0b = 0.f, s1a = 0.f, s1b = 0.f;
    float o0a = 0.f, o0b = 0.f, o1a = 0.f, o1b = 0.f;

    if (d < 4) {
        #pragma unroll
        for (int jy = 0; jy < KS; jy++) {
            const float2* kp = (const float2*)(ks_ + (r + jy)*SP + w0);
            const float2* vp = (const float2*)(vs_ + (r + jy)*SP + w0);
            float2 ka = kp[0], kc = kp[1], ke = kp[2], kg = kp[3];
            float2 va = vp[0], vc = vp[1], ve = vp[2], vg = vp[3];
            float a0 = q0 * relv[jy];
            float a1 = q1 * relv[jy];
            float e;
            EX2F(e, fmaf(q0, ka.x, a0)); s0a += e; o0a = fmaf(e, va.x, o0a);
            EX2F(e, fmaf(q0, ka.y, a0)); s0b += e; o0b = fmaf(e, va.y, o0b);
            EX2F(e, fmaf(q0, kc.x, a0)); s0a += e; o0a = fmaf(e, vc.x, o0a);
            EX2F(e, fmaf(q0, kc.y, a0)); s0b += e; o0b = fmaf(e, vc.y, o0b);
            EX2F(e, fmaf(q0, ke.x, a0)); s0a += e; o0a = fmaf(e, ve.x, o0a);
            EX2F(e, fmaf(q0, ke.y, a0)); s0b += e; o0b = fmaf(e, ve.y, o0b);
            EX2F(e, fmaf(q0, kg.x, a0)); s0a += e; o0a = fmaf(e, vg.x, o0a);
            EX2F(e, fmaf(q1, ka.y, a1)); s1a += e; o1a = fmaf(e, va.y, o1a);
            EX2F(e, fmaf(q1, kc.x, a1)); s1b += e; o1b = fmaf(e, vc.x, o1b);
            EX2F(e, fmaf(q1, kc.y, a1)); s1a += e; o1a = fmaf(e, vc.y, o1a);
            EX2F(e, fmaf(q1, ke.x, a1)); s1b += e; o1b = fmaf(e, ve.x, o1b);
            EX2F(e, fmaf(q1, ke.y, a1)); s1a += e; o1a = fmaf(e, ve.y, o1a);
            EX2F(e, fmaf(q1, kg.x, a1)); s1b += e; o1b = fmaf(e, vg.x, o1b);
            EX2F(e, fmaf(q1, kg.y, a1)); s1a += e; o1a = fmaf(e, vg.y, o1a);
        }
    } else {
        #pragma unroll
        for (int jy = 0; jy < KS; jy++) {
            const float2* kp = (const float2*)(ks_ + (r + jy)*SP + w0);
            const float2* vp = (const float2*)(vs_ + (r + jy)*SP + w0);
            float2 ka = kp[0], kc = kp[1], ke = kp[2], kg = kp[3];
            float2 va = vp[0], vc = vp[1], ve = vp[2], vg = vp[3];
            float e;
            EX2F(e, fmaf(q0, ka.x, q0*relv[0])); s0a += e; o0a = fmaf(e, va.x, o0a);
            EX2F(e, fmaf(q0, ka.y, q0*relv[1])); s0b += e; o0b = fmaf(e, va.y, o0b);
            EX2F(e, fmaf(q0, kc.x, q0*relv[2])); s0a += e; o0a = fmaf(e, vc.x, o0a);
            EX2F(e, fmaf(q0, kc.y, q0*relv[3])); s0b += e; o0b = fmaf(e, vc.y, o0b);
            EX2F(e, fmaf(q0, ke.x, q0*relv[4])); s0a += e; o0a = fmaf(e, ve.x, o0a);
            EX2F(e, fmaf(q0, ke.y, q0*relv[5])); s0b += e; o0b = fmaf(e, ve.y, o0b);
            EX2F(e, fmaf(q0, kg.x, q0*relv[6])); s0a += e; o0a = fmaf(e, vg.x, o0a);
            EX2F(e, fmaf(q1, ka.y, q1*relv[0])); s1a += e; o1a = fmaf(e, va.y, o1a);
            EX2F(e, fmaf(q1, kc.x, q1*relv[1])); s1b += e; o1b = fmaf(e, vc.x, o1b);
            EX2F(e, fmaf(q1, kc.y, q1*relv[2])); s1a += e; o1a = fmaf(e, vc.y, o1a);
            EX2F(e, fmaf(q1, ke.x, q1*relv[3])); s1b += e; o1b = fmaf(e, ve.x, o1b);
            EX2F(e, fmaf(q1, ke.y, q1*relv[4])); s1a += e; o1a = fmaf(e, ve.y, o1a);
            EX2F(e, fmaf(q1, kg.x, q1*relv[5])); s1b += e; o1b = fmaf(e, vg.x, o1b);
            EX2F(e, fmaf(q1, kg.y, q1*relv[6])); s1a += e; o1a = fmaf(e, vg.y, o1a);
        }
    }

    float2 res;
    res.x = __fdividef(o0a + o0b, s0a + s0b);
    res.y = __fdividef(o1a + o1b, s1a + s1b);
    *(float2*)&out[(cbase + h)*W + w0] = res;
}

// ---------------------------------------------------------------------------
extern "C" void kernel_launch(void* const* d_in, const int* in_sizes, int n_in,
                              void* d_out, int out_size) {
    const float* x     = (const float*)d_in[0];
    const float* wq    = (const float*)d_in[1];
    const float* wk    = (const float*)d_in[2];
    const float* bk    = (const float*)d_in[3];
    const float* wv    = (const float*)d_in[4];
    const float* bv    = (const float*)d_in[5];
    const float* rel_x = (const float*)d_in[6];
    const float* rel_y = (const float*)d_in[7];
    float* out = (float*)d_out;

    qkv_kernel<<<392, 256>>>(x, wq, wk, bk, wv, bv);   // conv + halo fill

    dim3 grid(H/TH, COUT, B);   // 1792 blocks
    attn_kernel<<<grid, 224>>>(rel_x, rel_y, out);
}